// round 13
// baseline (speedup 1.0000x reference)
#include <cuda_runtime.h>
#include <cstdint>

// Problem dims (fixed by the dataset)
#define TOK    2048   // B*S
#define DMODEL 512
#define NIN    2048
#define NPROC  1024
#define DPV    256
#define NOUT   2048
#define KIN    256
#define KPROC  128
#define KOUT   256

// Scratch (device globals — no dynamic allocation allowed)
__device__ float g_acts1[TOK * NIN];      // gelu(x @ IP^T)       16 MB
__device__ float g_Wt[NIN * NPROC];       // PIW^T                 8 MB
__device__ float g_xT[DMODEL * TOK];      // x^T   (k-major A)     4 MB
__device__ float g_ipT[DMODEL * NIN];     // IP^T  (k-major B)     4 MB
__device__ float g_oiwT[DPV * NOUT];      // OIW^T (k-major B)     2 MB
__device__ float g_aggT[DPV * TOK];       // agg^T (k-major A)     2 MB
__device__ float g_acts3[TOK * NOUT];     // gelu(agg @ OIW^T)    16 MB

// ---------------------------------------------------------------------------
// XLA's f32 erf (what jax.lax.erf runs): clamp to [-4,4], x*P(x^2)/Q(x^2).
// ---------------------------------------------------------------------------
__device__ __forceinline__ float erf_xla(float x) {
    x = fminf(fmaxf(x, -4.0f), 4.0f);
    float x2 = x * x;
    float p = fmaf(x2, 0.00022905065861350646f, 0.0034082910107109506f);
    p = fmaf(x2, p, 0.050955695062380861f);
    p = fmaf(x2, p, 0.18520832239976145f);
    p = fmaf(x2, p, 1.128379143519084f);
    p = x * p;
    float q = fmaf(x2, -1.1791602954361697e-7f, 2.3547966471313185e-05f);
    q = fmaf(x2, q, 0.0010179625278914885f);
    q = fmaf(x2, q, 0.014070470171167667f);
    q = fmaf(x2, q, 0.11098505178285362f);
    q = fmaf(x2, q, 0.49746925110067538f);
    q = fmaf(x2, q, 1.0f);
    return __fdiv_rn(p, q);
}

// jax.nn.gelu(approximate=False): (x * (erf(x / sqrt2) + 1)) / 2
__device__ __forceinline__ float gelu_f(float x) {
    float t = __fdiv_rn(x, 1.41421356237309504880f);
    float e = erf_xla(t);
    return x * (e + 1.0f) * 0.5f;
}

// order-preserving float -> uint key (larger float => larger key)
__device__ __forceinline__ unsigned fkey(float f) {
    unsigned b = __float_as_uint(f);
    return b ^ ((b & 0x80000000u) ? 0xFFFFFFFFu : 0x80000000u);
}

// ---------------------------------------------------------------------------
// Packed f32x2 helpers. Each half = independent IEEE rn FMA, bitwise
// identical to scalar fmaf on that half.
// ---------------------------------------------------------------------------
__device__ __forceinline__ void ffma2(unsigned long long& d,
                                      unsigned long long a,
                                      unsigned long long b) {
    asm("fma.rn.f32x2 %0, %1, %2, %0;" : "+l"(d) : "l"(a), "l"(b));
}
__device__ __forceinline__ unsigned long long dup2(float x) {
    unsigned long long r;
    asm("mov.b64 %0, {%1, %1};" : "=l"(r) : "f"(x));
    return r;
}
__device__ __forceinline__ float2 unpack2(unsigned long long v) {
    float2 f;
    asm("mov.b64 {%0, %1}, %2;" : "=f"(f.x), "=f"(f.y) : "l"(v));
    return f;
}

// cp.async helpers
__device__ __forceinline__ void cp16(uint32_t smem, const void* g) {
    asm volatile("cp.async.ca.shared.global [%0], [%1], 16;"
                 :: "r"(smem), "l"(g));
}
__device__ __forceinline__ void cp_commit() {
    asm volatile("cp.async.commit_group;");
}
__device__ __forceinline__ void cp_wait1() {
    asm volatile("cp.async.wait_group 1;");
}

// ---------------------------------------------------------------------------
// Warp-shuffle scan primitives
// ---------------------------------------------------------------------------
__device__ __forceinline__ unsigned warp_suffix_incl(unsigned v, int lane) {
    #pragma unroll
    for (int off = 1; off < 32; off <<= 1) {
        unsigned o = __shfl_down_sync(0xffffffffu, v, off);
        if (lane + off < 32) v += o;
    }
    return v;
}
__device__ __forceinline__ unsigned warp_prefix_incl(unsigned v, int lane) {
    #pragma unroll
    for (int off = 1; off < 32; off <<= 1) {
        unsigned o = __shfl_up_sync(0xffffffffu, v, off);
        if (lane >= off) v += o;
    }
    return v;
}

// block-wide (256 thr) exclusive prefix sum; s_wsum is 8-entry scratch
__device__ __forceinline__ unsigned block_prefix_excl(unsigned x, unsigned* s_wsum) {
    const int tid = threadIdx.x, lane = tid & 31, wid = tid >> 5;
    unsigned v = warp_prefix_incl(x, lane);
    __syncthreads();
    if (lane == 31) s_wsum[wid] = v;
    __syncthreads();
    unsigned add = 0;
    #pragma unroll
    for (int w = 0; w < 8; ++w) if (w < wid) add += s_wsum[w];
    return v + add - x;
}

// ---------------------------------------------------------------------------
// Exact top-k for one row in shared memory. Block = 256 threads.
// jax.lax.top_k set semantics (lowest index wins ties); slots in
// ascending-index order. n = EPB*256.
// ---------------------------------------------------------------------------
template <int EPB>
__device__ void topk_fast(const float* sdata, int k, int* out_idx, float* out_val)
{
    __shared__ unsigned s_cnt[256];
    __shared__ unsigned s_wsum[8];
    __shared__ unsigned s_bin;
    __shared__ unsigned s_kneed;
    const int tid  = threadIdx.x, lane = tid & 31, wid = tid >> 5;
    const int base = tid * EPB;

    unsigned key[EPB];
    #pragma unroll
    for (int e = 0; e < EPB; ++e) key[e] = fkey(sdata[base + e]);

    if (tid == 0) s_kneed = (unsigned)k;
    unsigned prefix = 0;

    #pragma unroll
    for (int pass = 0; pass < 4; ++pass) {
        const int shift = 24 - 8 * pass;
        s_cnt[tid] = 0;
        __syncthreads();
        #pragma unroll
        for (int e = 0; e < EPB; ++e) {
            bool m;
            if (pass == 0) m = true;
            else           m = ((key[e] >> (shift + 8)) == prefix);
            if (m) atomicAdd(&s_cnt[(key[e] >> shift) & 255u], 1u);
        }
        __syncthreads();
        unsigned own = s_cnt[tid];
        unsigned v   = warp_suffix_incl(own, lane);   // lane0 = warp total
        if (lane == 0) s_wsum[wid] = v;
        __syncthreads();
        unsigned add = 0;
        #pragma unroll
        for (int w = 0; w < 8; ++w) if (w > wid) add += s_wsum[w];
        v += add;                                     // inclusive suffix over 256 bins
        unsigned kneed = s_kneed;
        __syncthreads();
        if (v >= kneed && (v - own) < kneed) {
            s_bin   = (unsigned)tid;
            s_kneed = kneed - (v - own);
        }
        __syncthreads();
        prefix = (prefix << 8) | s_bin;
    }
    const unsigned thr = prefix;
    const unsigned r   = s_kneed;

    unsigned ceq = 0, cgt = 0;
    #pragma unroll
    for (int e = 0; e < EPB; ++e) {
        if (key[e] > thr) cgt++;
        else if (key[e] == thr) ceq++;
    }
    unsigned eq_base = block_prefix_excl(ceq, s_wsum);
    unsigned eq_keep = (eq_base < r) ? min(r - eq_base, ceq) : 0u;
    unsigned slot    = block_prefix_excl(cgt + eq_keep, s_wsum);

    unsigned eqo = eq_base;
    #pragma unroll
    for (int e = 0; e < EPB; ++e) {
        bool keep = false;
        if (key[e] > thr) keep = true;
        else if (key[e] == thr) { keep = (eqo < r); eqo++; }
        if (keep) { out_idx[slot] = base + e; out_val[slot] = sdata[base + e]; slot++; }
    }
    __syncthreads();
}

// ---------------------------------------------------------------------------
// Bitonic sort of (val,idx) pairs, length L (power of 2 <= 256), 256 threads.
// Final order: descending value; ties -> ascending index (jax top_k order).
// ---------------------------------------------------------------------------
__device__ void sort_desc(float* v, int* idx, int L) {
    const int tid = threadIdx.x;
    for (int size = 2; size <= L; size <<= 1) {
        for (int stride = size >> 1; stride > 0; stride >>= 1) {
            __syncthreads();
            for (int i = tid; i < (L >> 1); i += 256) {
                int lo = 2 * i - (i & (stride - 1));
                int hi = lo + stride;
                float va = v[lo], vb = v[hi];
                int   ia = idx[lo], ib = idx[hi];
                bool aBeforeB = (va > vb) || (va == vb && ia < ib);
                bool dirDesc  = ((lo & size) == 0);
                if (dirDesc ? !aBeforeB : aBeforeB) {
                    v[lo] = vb; v[hi] = va;
                    idx[lo] = ib; idx[hi] = ia;
                }
            }
        }
    }
    __syncthreads();
}

// ---------------------------------------------------------------------------
// All four input transposes fused in one launch.
// ---------------------------------------------------------------------------
__global__ void k_transp_all(const float* __restrict__ x,
                             const float* __restrict__ ip,
                             const float* __restrict__ oiw,
                             const float* __restrict__ piw) {
    __shared__ float tile[32][33];
    int b = blockIdx.x;
    const float* src; float* dst; int R, C, bx, by;
    if (b < 1024)      { src = x;   dst = g_xT;   R = TOK;   C = DMODEL; bx = b & 15;  by = b >> 4; }
    else if (b < 2048) { b -= 1024; src = ip;  dst = g_ipT;  R = NIN;   C = DMODEL; bx = b & 15;  by = b >> 4; }
    else if (b < 2560) { b -= 2048; src = oiw; dst = g_oiwT; R = NOUT;  C = DPV;    bx = b & 7;   by = b >> 3; }
    else               { b -= 2560; src = piw; dst = g_Wt;   R = NPROC; C = NIN;    bx = b & 63;  by = b >> 6; }
    int c0 = bx * 32, r0 = by * 32;
    int tx = threadIdx.x, ty = threadIdx.y;
    #pragma unroll
    for (int j = 0; j < 32; j += 8)
        tile[ty + j][tx] = src[(size_t)(r0 + ty + j) * C + c0 + tx];
    __syncthreads();
    #pragma unroll
    for (int j = 0; j < 32; j += 8)
        dst[(size_t)(c0 + ty + j) * R + r0 + tx] = tile[tx][ty + j];
}

// ---------------------------------------------------------------------------
// GEMM with k-major operands (fp32 MAC roofline). m0_off selects token half.
// ---------------------------------------------------------------------------
template <int K>
__global__ __launch_bounds__(256, 2) void k_gemm(
    const float* __restrict__ At,   // [K][Mtot]
    const float* __restrict__ Bt,   // [K][Ntot]
    float* __restrict__ C,          // [Mtot][Ntot]
    int Mtot, int Ntot, int m0_off)
{
    constexpr int BK = 32, STAGES = 3, NT = K / BK;
    constexpr int TILE_FLOATS = BK * 128;
    extern __shared__ __align__(16) float smem_dyn[];
    float* sAq = smem_dyn;
    float* sBq = smem_dyn + STAGES * TILE_FLOATS;
    const int tid = threadIdx.x;
    const int tx  = tid & 15, ty = tid >> 4;
    const int m0  = m0_off + blockIdx.y * 128;
    const int n0  = blockIdx.x * 128;

    const int cr = tid >> 5;
    const int cc = (tid & 31) << 2;
    const uint32_t sA0 = (uint32_t)__cvta_generic_to_shared(sAq);
    const uint32_t sB0 = (uint32_t)__cvta_generic_to_shared(sBq);
    uint32_t so[4];
    #pragma unroll
    for (int i = 0; i < 4; ++i) so[i] = (uint32_t)(((cr + 8 * i) * 128 + cc) * 4);

    unsigned long long acc2[8][4];
    #pragma unroll
    for (int i = 0; i < 8; ++i)
        #pragma unroll
        for (int j = 0; j < 4; ++j) acc2[i][j] = 0ull;

    #pragma unroll
    for (int s = 0; s < STAGES - 1; ++s) {
        const size_t gk = (size_t)s * BK;
        #pragma unroll
        for (int i = 0; i < 4; ++i) {
            cp16(sA0 + s * (TILE_FLOATS * 4) + so[i],
                 At + (gk + cr + 8 * i) * (size_t)Mtot + m0 + cc);
            cp16(sB0 + s * (TILE_FLOATS * 4) + so[i],
                 Bt + (gk + cr + 8 * i) * (size_t)Ntot + n0 + cc);
        }
        cp_commit();
    }

    int stage = 0;
    for (int kt = 0; kt < NT; ++kt) {
        cp_wait1();
        __syncthreads();

        if (kt + STAGES - 1 < NT) {
            int ps = (stage + STAGES - 1) % STAGES;
            const size_t gk = (size_t)(kt + STAGES - 1) * BK;
            #pragma unroll
            for (int i = 0; i < 4; ++i) {
                cp16(sA0 + ps * (TILE_FLOATS * 4) + so[i],
                     At + (gk + cr + 8 * i) * (size_t)Mtot + m0 + cc);
                cp16(sB0 + ps * (TILE_FLOATS * 4) + so[i],
                     Bt + (gk + cr + 8 * i) * (size_t)Ntot + n0 + cc);
            }
        }
        cp_commit();

        const float* a_s = sAq + stage * TILE_FLOATS;
        const float* b_s = sBq + stage * TILE_FLOATS;
        #pragma unroll
        for (int kk = 0; kk < BK; ++kk) {
            float4 a0 = *(const float4*)&a_s[kk * 128 + ty * 8];
            float4 a1 = *(const float4*)&a_s[kk * 128 + ty * 8 + 4];
            ulonglong2 b01 = *(const ulonglong2*)&b_s[kk * 128 + tx * 8];
            ulonglong2 b23 = *(const ulonglong2*)&b_s[kk * 128 + tx * 8 + 4];
            unsigned long long bb[4] = {b01.x, b01.y, b23.x, b23.y};
            float ar[8] = {a0.x, a0.y, a0.z, a0.w, a1.x, a1.y, a1.z, a1.w};
            #pragma unroll
            for (int i = 0; i < 8; ++i) {
                unsigned long long ad = dup2(ar[i]);
                #pragma unroll
                for (int j = 0; j < 4; ++j)
                    ffma2(acc2[i][j], ad, bb[j]);
            }
        }
        stage = (stage + 1) % STAGES;
    }

    #pragma unroll
    for (int i = 0; i < 8; ++i) {
        float* Cr = C + (size_t)(m0 + ty * 8 + i) * Ntot + n0 + tx * 8;
        float2 p0 = unpack2(acc2[i][0]);
        float2 p1 = unpack2(acc2[i][1]);
        float2 p2 = unpack2(acc2[i][2]);
        float2 p3 = unpack2(acc2[i][3]);
        float4 o0, o1;
        o0.x = gelu_f(p0.x); o0.y = gelu_f(p0.y);
        o0.z = gelu_f(p1.x); o0.w = gelu_f(p1.y);
        o1.x = gelu_f(p2.x); o1.y = gelu_f(p2.y);
        o1.z = gelu_f(p3.x); o1.w = gelu_f(p3.y);
        *(float4*)Cr       = o0;
        *(float4*)(Cr + 4) = o1;
    }
}

// ---------------------------------------------------------------------------
// Stage 1+2 fused (R11 version): acts1 row -> top-256 -> L2 gather-matmul
// (FFMA2 col pairs {2t,2t+1},{2t+512,2t+513}, ascending-n chains) -> gelu ->
// top-128 -> sort desc -> softmax (sequential, jax order) -> PV gather.
// toff selects token half.
// ---------------------------------------------------------------------------
__global__ __launch_bounds__(256) void k_stage2(const float* __restrict__ PV,
                                                int toff) {
    __shared__ float sdata[NIN];
    __shared__ int   sIdx[KIN];
    __shared__ float sVal[KIN];
    __shared__ int   pidx[KPROC];
    __shared__ float pval[KPROC];
    __shared__ float sexp[KPROC];
    __shared__ float sdenom;
    const int t   = toff + blockIdx.x;
    const int tid = threadIdx.x;

    {
        const float4* row = (const float4*)(g_acts1 + (size_t)t * NIN);
        float4 r0 = row[tid];
        float4 r1 = row[tid + 256];
        ((float4*)sdata)[tid]       = r0;
        ((float4*)sdata)[tid + 256] = r1;
    }
    __syncthreads();

    topk_fast<NIN / 256>(sdata, KIN, sIdx, sVal);

    unsigned long long A0 = 0ull, A1 = 0ull;   // col pairs (2tid,2tid+1), (+512)
    #pragma unroll 16
    for (int j = 0; j < KIN; ++j) {            // ascending n (reference order)
        const unsigned long long v = dup2(sVal[j]);
        const float* w = g_Wt + (size_t)sIdx[j] * NPROC;
        unsigned long long w0 = *(const unsigned long long*)(w + 2 * tid);
        unsigned long long w1 = *(const unsigned long long*)(w + 2 * tid + 512);
        ffma2(A0, v, w0);
        ffma2(A1, v, w1);
    }
    __syncthreads();
    {
        float2 p0 = unpack2(A0);
        float2 p1 = unpack2(A1);
        sdata[2 * tid]           = gelu_f(p0.x);
        sdata[2 * tid + 1]       = gelu_f(p0.y);
        sdata[2 * tid + 512]     = gelu_f(p1.x);
        sdata[2 * tid + 513]     = gelu_f(p1.y);
    }
    __syncthreads();

    topk_fast<NPROC / 256>(sdata, KPROC, pidx, pval);
    sort_desc(pval, pidx, KPROC);           // jax top_k output order

    if (tid < KPROC) sexp[tid] = expf(pval[tid] - pval[0]);
    __syncthreads();
    if (tid == 0) {
        float s = 0.f;
        for (int j = 0; j < KPROC; ++j) s += sexp[j];
        sdenom = s;
    }
    __syncthreads();
    const float denom = sdenom;
    if (tid < KPROC) pval[tid] = __fdiv_rn(sexp[tid], denom);
    __syncthreads();

    float acc = 0.f;
    #pragma unroll 16
    for (int j = 0; j < KPROC; ++j)
        acc = fmaf(pval[j], PV[(size_t)pidx[j] * DPV + tid], acc);
    g_aggT[(size_t)tid * TOK + t] = acc;    // transposed (k-major for gemm3)
}

// ---------------------------------------------------------------------------
// Stage 3 (R11 version): top-256 of 2048 + combine in ascending-index slot
// order, cols (2tid, 2tid+1) via FFMA2. toff selects token half.
// ---------------------------------------------------------------------------
__global__ __launch_bounds__(256) void k_stage3(const float* __restrict__ OP,
                                                float* __restrict__ out,
                                                int toff) {
    __shared__ float sdata[NOUT];
    __shared__ int   sidx[KOUT];
    __shared__ float sval[KOUT];
    const int t   = toff + blockIdx.x;
    const int tid = threadIdx.x;
    {
        const float4* row = (const float4*)(g_acts3 + (size_t)t * NOUT);
        ((float4*)sdata)[tid]       = row[tid];
        ((float4*)sdata)[tid + 256] = row[tid + 256];
    }
    __syncthreads();
    topk_fast<NOUT / 256>(sdata, KOUT, sidx, sval);

    unsigned long long A = 0ull;            // cols (2tid, 2tid+1)
    #pragma unroll 16
    for (int j = 0; j < KOUT; ++j) {        // ascending-index slot order
        const unsigned long long v = dup2(sval[j]);
        const float* p = OP + (size_t)sidx[j] * DMODEL;
        unsigned long long pw = *(const unsigned long long*)(p + 2 * tid);
        ffma2(A, v, pw);
    }
    float2 o = unpack2(A);
    *(float2*)(out + (size_t)t * DMODEL + 2 * tid) = o;
}

// persistent stream/events for the pipelined graph (host-side objects only)
static cudaStream_t g_s2 = nullptr;
static cudaEvent_t  g_evFork = nullptr, g_evJoin = nullptr;

extern "C" void kernel_launch(void* const* d_in, const int* in_sizes, int n_in,
                              void* d_out, int out_size) {
    const float* x   = (const float*)d_in[0];  // [2,1024,512]
    const float* ip  = (const float*)d_in[1];  // [2048,512]
    const float* piw = (const float*)d_in[2];  // [1024,2048]
    const float* pv  = (const float*)d_in[3];  // [1024,256]
    const float* oiw = (const float*)d_in[4];  // [2048,256]
    const float* op  = (const float*)d_in[5];  // [2048,512]
    float* out = (float*)d_out;                // [2,1024,512]

    float* xT   = nullptr; cudaGetSymbolAddress((void**)&xT,   g_xT);
    float* ipT  = nullptr; cudaGetSymbolAddress((void**)&ipT,  g_ipT);
    float* oiwT = nullptr; cudaGetSymbolAddress((void**)&oiwT, g_oiwT);
    float* a1p  = nullptr; cudaGetSymbolAddress((void**)&a1p,  g_acts1);
    float* aggT = nullptr; cudaGetSymbolAddress((void**)&aggT, g_aggT);
    float* a3p  = nullptr; cudaGetSymbolAddress((void**)&a3p,  g_acts3);

    const int GEMM_SMEM = 3 * 2 * 32 * 128 * 4;   // 96 KB
    static bool init_done = false;
    if (!init_done) {
        cudaFuncSetAttribute(k_gemm<DMODEL>,
            cudaFuncAttributeMaxDynamicSharedMemorySize, GEMM_SMEM);
        cudaFuncSetAttribute(k_gemm<DPV>,
            cudaFuncAttributeMaxDynamicSharedMemorySize, GEMM_SMEM);
        cudaStreamCreateWithFlags(&g_s2, cudaStreamNonBlocking);
        cudaEventCreateWithFlags(&g_evFork, cudaEventDisableTiming);
        cudaEventCreateWithFlags(&g_evJoin, cudaEventDisableTiming);
        init_done = true;
    }

    const int HTOK = TOK / 2;   // 1024

    // ---- stream 0 (capture stream): half A ------------------------------
    k_transp_all<<<4608, dim3(32, 8)>>>(x, ip, oiw, piw);
    k_gemm<DMODEL><<<dim3(NIN / 128, HTOK / 128), 256, GEMM_SMEM>>>(
        xT, ipT, a1p, TOK, NIN, 0);

    // fork: half B proceeds on g_s2 once transp+gemm1(A) are done
    cudaEventRecord(g_evFork, 0);
    cudaStreamWaitEvent(g_s2, g_evFork, 0);

    // ---- stream g_s2: half B -------------------------------------------
    k_gemm<DMODEL><<<dim3(NIN / 128, HTOK / 128), 256, GEMM_SMEM, g_s2>>>(
        xT, ipT, a1p, TOK, NIN, HTOK);
    k_stage2<<<HTOK, 256, 0, g_s2>>>(pv, HTOK);
    k_gemm<DPV><<<dim3(NOUT / 128, HTOK / 128), 256, GEMM_SMEM, g_s2>>>(
        aggT, oiwT, a3p, TOK, NOUT, HTOK);
    k_stage3<<<HTOK, 256, 0, g_s2>>>(op, out, HTOK);

    // ---- stream 0 continues: half A ------------------------------------
    k_stage2<<<HTOK, 256>>>(pv, 0);
    k_gemm<DPV><<<dim3(NOUT / 128, HTOK / 128), 256, GEMM_SMEM>>>(
        aggT, oiwT, a3p, TOK, NOUT, 0);
    k_stage3<<<HTOK, 256>>>(op, out, 0);

    // join: stream 0 waits for half B before returning
    cudaEventRecord(g_evJoin, g_s2);
    cudaStreamWaitEvent(0, g_evJoin, 0);
}

// round 14
// speedup vs baseline: 1.4333x; 1.4333x over previous
#include <cuda_runtime.h>
#include <cstdint>

// Problem dims (fixed by the dataset)
#define TOK    2048   // B*S
#define DMODEL 512
#define NIN    2048
#define NPROC  1024
#define DPV    256
#define NOUT   2048
#define KIN    256
#define KPROC  128
#define KOUT   256

// Scratch (device globals — no dynamic allocation allowed)
__device__ float g_acts1[TOK * NIN];      // gelu(x @ IP^T)       16 MB
__device__ float g_Wt[NIN * NPROC];       // PIW^T                 8 MB
__device__ float g_xT[DMODEL * TOK];      // x^T   (k-major A)     4 MB
__device__ float g_ipT[DMODEL * NIN];     // IP^T  (k-major B)     4 MB
__device__ float g_oiwT[DPV * NOUT];      // OIW^T (k-major B)     2 MB
__device__ float g_aggT[DPV * TOK];       // agg^T (k-major A)     2 MB
__device__ float g_acts3[TOK * NOUT];     // gelu(agg @ OIW^T)    16 MB

// ---------------------------------------------------------------------------
// XLA's f32 erf (what jax.lax.erf runs): clamp to [-4,4], x*P(x^2)/Q(x^2).
// ---------------------------------------------------------------------------
__device__ __forceinline__ float erf_xla(float x) {
    x = fminf(fmaxf(x, -4.0f), 4.0f);
    float x2 = x * x;
    float p = fmaf(x2, 0.00022905065861350646f, 0.0034082910107109506f);
    p = fmaf(x2, p, 0.050955695062380861f);
    p = fmaf(x2, p, 0.18520832239976145f);
    p = fmaf(x2, p, 1.128379143519084f);
    p = x * p;
    float q = fmaf(x2, -1.1791602954361697e-7f, 2.3547966471313185e-05f);
    q = fmaf(x2, q, 0.0010179625278914885f);
    q = fmaf(x2, q, 0.014070470171167667f);
    q = fmaf(x2, q, 0.11098505178285362f);
    q = fmaf(x2, q, 0.49746925110067538f);
    q = fmaf(x2, q, 1.0f);
    return __fdiv_rn(p, q);
}

// jax.nn.gelu(approximate=False): (x * (erf(x / sqrt2) + 1)) / 2
__device__ __forceinline__ float gelu_f(float x) {
    float t = __fdiv_rn(x, 1.41421356237309504880f);
    float e = erf_xla(t);
    return x * (e + 1.0f) * 0.5f;
}

// order-preserving float -> uint key (larger float => larger key)
__device__ __forceinline__ unsigned fkey(float f) {
    unsigned b = __float_as_uint(f);
    return b ^ ((b & 0x80000000u) ? 0xFFFFFFFFu : 0x80000000u);
}

// ---------------------------------------------------------------------------
// Packed f32x2 helpers. Each half = independent IEEE rn FMA, bitwise
// identical to scalar fmaf on that half.
// ---------------------------------------------------------------------------
__device__ __forceinline__ void ffma2(unsigned long long& d,
                                      unsigned long long a,
                                      unsigned long long b) {
    asm("fma.rn.f32x2 %0, %1, %2, %0;" : "+l"(d) : "l"(a), "l"(b));
}
__device__ __forceinline__ unsigned long long dup2(float x) {
    unsigned long long r;
    asm("mov.b64 %0, {%1, %1};" : "=l"(r) : "f"(x));
    return r;
}
__device__ __forceinline__ float2 unpack2(unsigned long long v) {
    float2 f;
    asm("mov.b64 {%0, %1}, %2;" : "=f"(f.x), "=f"(f.y) : "l"(v));
    return f;
}

// cp.async helpers
__device__ __forceinline__ void cp16(uint32_t smem, const void* g) {
    asm volatile("cp.async.ca.shared.global [%0], [%1], 16;"
                 :: "r"(smem), "l"(g));
}
__device__ __forceinline__ void cp_commit() {
    asm volatile("cp.async.commit_group;");
}
__device__ __forceinline__ void cp_wait1() {
    asm volatile("cp.async.wait_group 1;");
}

// ---------------------------------------------------------------------------
// Warp-shuffle scan primitives
// ---------------------------------------------------------------------------
__device__ __forceinline__ unsigned warp_suffix_incl(unsigned v, int lane) {
    #pragma unroll
    for (int off = 1; off < 32; off <<= 1) {
        unsigned o = __shfl_down_sync(0xffffffffu, v, off);
        if (lane + off < 32) v += o;
    }
    return v;
}
__device__ __forceinline__ unsigned warp_prefix_incl(unsigned v, int lane) {
    #pragma unroll
    for (int off = 1; off < 32; off <<= 1) {
        unsigned o = __shfl_up_sync(0xffffffffu, v, off);
        if (lane >= off) v += o;
    }
    return v;
}

// block-wide (256 thr) exclusive prefix sum; s_wsum is 8-entry scratch
__device__ __forceinline__ unsigned block_prefix_excl(unsigned x, unsigned* s_wsum) {
    const int tid = threadIdx.x, lane = tid & 31, wid = tid >> 5;
    unsigned v = warp_prefix_incl(x, lane);
    __syncthreads();
    if (lane == 31) s_wsum[wid] = v;
    __syncthreads();
    unsigned add = 0;
    #pragma unroll
    for (int w = 0; w < 8; ++w) if (w < wid) add += s_wsum[w];
    return v + add - x;
}

// ---------------------------------------------------------------------------
// Exact top-k for one row in shared memory. Block = 256 threads.
// jax.lax.top_k set semantics (lowest index wins ties); slots in
// ascending-index order. n = EPB*256.
// ---------------------------------------------------------------------------
template <int EPB>
__device__ void topk_fast(const float* sdata, int k, int* out_idx, float* out_val)
{
    __shared__ unsigned s_cnt[256];
    __shared__ unsigned s_wsum[8];
    __shared__ unsigned s_bin;
    __shared__ unsigned s_kneed;
    const int tid  = threadIdx.x, lane = tid & 31, wid = tid >> 5;
    const int base = tid * EPB;

    unsigned key[EPB];
    #pragma unroll
    for (int e = 0; e < EPB; ++e) key[e] = fkey(sdata[base + e]);

    if (tid == 0) s_kneed = (unsigned)k;
    unsigned prefix = 0;

    #pragma unroll
    for (int pass = 0; pass < 4; ++pass) {
        const int shift = 24 - 8 * pass;
        s_cnt[tid] = 0;
        __syncthreads();
        #pragma unroll
        for (int e = 0; e < EPB; ++e) {
            bool m;
            if (pass == 0) m = true;
            else           m = ((key[e] >> (shift + 8)) == prefix);
            if (m) atomicAdd(&s_cnt[(key[e] >> shift) & 255u], 1u);
        }
        __syncthreads();
        unsigned own = s_cnt[tid];
        unsigned v   = warp_suffix_incl(own, lane);   // lane0 = warp total
        if (lane == 0) s_wsum[wid] = v;
        __syncthreads();
        unsigned add = 0;
        #pragma unroll
        for (int w = 0; w < 8; ++w) if (w > wid) add += s_wsum[w];
        v += add;                                     // inclusive suffix over 256 bins
        unsigned kneed = s_kneed;
        __syncthreads();
        if (v >= kneed && (v - own) < kneed) {
            s_bin   = (unsigned)tid;
            s_kneed = kneed - (v - own);
        }
        __syncthreads();
        prefix = (prefix << 8) | s_bin;
    }
    const unsigned thr = prefix;
    const unsigned r   = s_kneed;

    unsigned ceq = 0, cgt = 0;
    #pragma unroll
    for (int e = 0; e < EPB; ++e) {
        if (key[e] > thr) cgt++;
        else if (key[e] == thr) ceq++;
    }
    unsigned eq_base = block_prefix_excl(ceq, s_wsum);
    unsigned eq_keep = (eq_base < r) ? min(r - eq_base, ceq) : 0u;
    unsigned slot    = block_prefix_excl(cgt + eq_keep, s_wsum);

    unsigned eqo = eq_base;
    #pragma unroll
    for (int e = 0; e < EPB; ++e) {
        bool keep = false;
        if (key[e] > thr) keep = true;
        else if (key[e] == thr) { keep = (eqo < r); eqo++; }
        if (keep) { out_idx[slot] = base + e; out_val[slot] = sdata[base + e]; slot++; }
    }
    __syncthreads();
}

// ---------------------------------------------------------------------------
// Bitonic sort of (val,idx) pairs, length L (power of 2 <= 256), 256 threads.
// Final order: descending value; ties -> ascending index (jax top_k order).
// ---------------------------------------------------------------------------
__device__ void sort_desc(float* v, int* idx, int L) {
    const int tid = threadIdx.x;
    for (int size = 2; size <= L; size <<= 1) {
        for (int stride = size >> 1; stride > 0; stride >>= 1) {
            __syncthreads();
            for (int i = tid; i < (L >> 1); i += 256) {
                int lo = 2 * i - (i & (stride - 1));
                int hi = lo + stride;
                float va = v[lo], vb = v[hi];
                int   ia = idx[lo], ib = idx[hi];
                bool aBeforeB = (va > vb) || (va == vb && ia < ib);
                bool dirDesc  = ((lo & size) == 0);
                if (dirDesc ? !aBeforeB : aBeforeB) {
                    v[lo] = vb; v[hi] = va;
                    idx[lo] = ib; idx[hi] = ia;
                }
            }
        }
    }
    __syncthreads();
}

// ---------------------------------------------------------------------------
// All four input transposes fused in one launch.
// ---------------------------------------------------------------------------
__global__ void k_transp_all(const float* __restrict__ x,
                             const float* __restrict__ ip,
                             const float* __restrict__ oiw,
                             const float* __restrict__ piw) {
    __shared__ float tile[32][33];
    int b = blockIdx.x;
    const float* src; float* dst; int R, C, bx, by;
    if (b < 1024)      { src = x;   dst = g_xT;   R = TOK;   C = DMODEL; bx = b & 15;  by = b >> 4; }
    else if (b < 2048) { b -= 1024; src = ip;  dst = g_ipT;  R = NIN;   C = DMODEL; bx = b & 15;  by = b >> 4; }
    else if (b < 2560) { b -= 2048; src = oiw; dst = g_oiwT; R = NOUT;  C = DPV;    bx = b & 7;   by = b >> 3; }
    else               { b -= 2560; src = piw; dst = g_Wt;   R = NPROC; C = NIN;    bx = b & 63;  by = b >> 6; }
    int c0 = bx * 32, r0 = by * 32;
    int tx = threadIdx.x, ty = threadIdx.y;
    #pragma unroll
    for (int j = 0; j < 32; j += 8)
        tile[ty + j][tx] = src[(size_t)(r0 + ty + j) * C + c0 + tx];
    __syncthreads();
    #pragma unroll
    for (int j = 0; j < 32; j += 8)
        dst[(size_t)(c0 + ty + j) * R + r0 + tx] = tile[tx][ty + j];
}

// ---------------------------------------------------------------------------
// GEMM with k-major operands (fp32 MAC roofline). m0_off selects token range.
// ---------------------------------------------------------------------------
template <int K>
__global__ __launch_bounds__(256, 2) void k_gemm(
    const float* __restrict__ At,   // [K][Mtot]
    const float* __restrict__ Bt,   // [K][Ntot]
    float* __restrict__ C,          // [Mtot][Ntot]
    int Mtot, int Ntot, int m0_off)
{
    constexpr int BK = 32, STAGES = 3, NT = K / BK;
    constexpr int TILE_FLOATS = BK * 128;
    extern __shared__ __align__(16) float smem_dyn[];
    float* sAq = smem_dyn;
    float* sBq = smem_dyn + STAGES * TILE_FLOATS;
    const int tid = threadIdx.x;
    const int tx  = tid & 15, ty = tid >> 4;
    const int m0  = m0_off + blockIdx.y * 128;
    const int n0  = blockIdx.x * 128;

    const int cr = tid >> 5;
    const int cc = (tid & 31) << 2;
    const uint32_t sA0 = (uint32_t)__cvta_generic_to_shared(sAq);
    const uint32_t sB0 = (uint32_t)__cvta_generic_to_shared(sBq);
    uint32_t so[4];
    #pragma unroll
    for (int i = 0; i < 4; ++i) so[i] = (uint32_t)(((cr + 8 * i) * 128 + cc) * 4);

    unsigned long long acc2[8][4];
    #pragma unroll
    for (int i = 0; i < 8; ++i)
        #pragma unroll
        for (int j = 0; j < 4; ++j) acc2[i][j] = 0ull;

    #pragma unroll
    for (int s = 0; s < STAGES - 1; ++s) {
        const size_t gk = (size_t)s * BK;
        #pragma unroll
        for (int i = 0; i < 4; ++i) {
            cp16(sA0 + s * (TILE_FLOATS * 4) + so[i],
                 At + (gk + cr + 8 * i) * (size_t)Mtot + m0 + cc);
            cp16(sB0 + s * (TILE_FLOATS * 4) + so[i],
                 Bt + (gk + cr + 8 * i) * (size_t)Ntot + n0 + cc);
        }
        cp_commit();
    }

    int stage = 0;
    for (int kt = 0; kt < NT; ++kt) {
        cp_wait1();
        __syncthreads();

        if (kt + STAGES - 1 < NT) {
            int ps = (stage + STAGES - 1) % STAGES;
            const size_t gk = (size_t)(kt + STAGES - 1) * BK;
            #pragma unroll
            for (int i = 0; i < 4; ++i) {
                cp16(sA0 + ps * (TILE_FLOATS * 4) + so[i],
                     At + (gk + cr + 8 * i) * (size_t)Mtot + m0 + cc);
                cp16(sB0 + ps * (TILE_FLOATS * 4) + so[i],
                     Bt + (gk + cr + 8 * i) * (size_t)Ntot + n0 + cc);
            }
        }
        cp_commit();

        const float* a_s = sAq + stage * TILE_FLOATS;
        const float* b_s = sBq + stage * TILE_FLOATS;
        #pragma unroll
        for (int kk = 0; kk < BK; ++kk) {
            float4 a0 = *(const float4*)&a_s[kk * 128 + ty * 8];
            float4 a1 = *(const float4*)&a_s[kk * 128 + ty * 8 + 4];
            ulonglong2 b01 = *(const ulonglong2*)&b_s[kk * 128 + tx * 8];
            ulonglong2 b23 = *(const ulonglong2*)&b_s[kk * 128 + tx * 8 + 4];
            unsigned long long bb[4] = {b01.x, b01.y, b23.x, b23.y};
            float ar[8] = {a0.x, a0.y, a0.z, a0.w, a1.x, a1.y, a1.z, a1.w};
            #pragma unroll
            for (int i = 0; i < 8; ++i) {
                unsigned long long ad = dup2(ar[i]);
                #pragma unroll
                for (int j = 0; j < 4; ++j)
                    ffma2(acc2[i][j], ad, bb[j]);
            }
        }
        stage = (stage + 1) % STAGES;
    }

    #pragma unroll
    for (int i = 0; i < 8; ++i) {
        float* Cr = C + (size_t)(m0 + ty * 8 + i) * Ntot + n0 + tx * 8;
        float2 p0 = unpack2(acc2[i][0]);
        float2 p1 = unpack2(acc2[i][1]);
        float2 p2 = unpack2(acc2[i][2]);
        float2 p3 = unpack2(acc2[i][3]);
        float4 o0, o1;
        o0.x = gelu_f(p0.x); o0.y = gelu_f(p0.y);
        o0.z = gelu_f(p1.x); o0.w = gelu_f(p1.y);
        o1.x = gelu_f(p2.x); o1.y = gelu_f(p2.y);
        o1.z = gelu_f(p3.x); o1.w = gelu_f(p3.y);
        *(float4*)Cr       = o0;
        *(float4*)(Cr + 4) = o1;
    }
}

// ---------------------------------------------------------------------------
// Stage 1+2 fused (R11 version, full grid): acts1 row -> top-256 -> L2
// gather-matmul (FFMA2 col pairs {2t,2t+1},{2t+512,2t+513}, ascending-n
// chains) -> gelu -> top-128 -> sort desc -> softmax (sequential, jax order)
// -> PV gather -> g_aggT.
// ---------------------------------------------------------------------------
__global__ __launch_bounds__(256) void k_stage2(const float* __restrict__ PV) {
    __shared__ float sdata[NIN];
    __shared__ int   sIdx[KIN];
    __shared__ float sVal[KIN];
    __shared__ int   pidx[KPROC];
    __shared__ float pval[KPROC];
    __shared__ float sexp[KPROC];
    __shared__ float sdenom;
    const int t   = blockIdx.x;
    const int tid = threadIdx.x;

    {
        const float4* row = (const float4*)(g_acts1 + (size_t)t * NIN);
        float4 r0 = row[tid];
        float4 r1 = row[tid + 256];
        ((float4*)sdata)[tid]       = r0;
        ((float4*)sdata)[tid + 256] = r1;
    }
    __syncthreads();

    topk_fast<NIN / 256>(sdata, KIN, sIdx, sVal);

    unsigned long long A0 = 0ull, A1 = 0ull;   // col pairs (2tid,2tid+1), (+512)
    #pragma unroll 16
    for (int j = 0; j < KIN; ++j) {            // ascending n (reference order)
        const unsigned long long v = dup2(sVal[j]);
        const float* w = g_Wt + (size_t)sIdx[j] * NPROC;
        unsigned long long w0 = *(const unsigned long long*)(w + 2 * tid);
        unsigned long long w1 = *(const unsigned long long*)(w + 2 * tid + 512);
        ffma2(A0, v, w0);
        ffma2(A1, v, w1);
    }
    __syncthreads();
    {
        float2 p0 = unpack2(A0);
        float2 p1 = unpack2(A1);
        sdata[2 * tid]           = gelu_f(p0.x);
        sdata[2 * tid + 1]       = gelu_f(p0.y);
        sdata[2 * tid + 512]     = gelu_f(p1.x);
        sdata[2 * tid + 513]     = gelu_f(p1.y);
    }
    __syncthreads();

    topk_fast<NPROC / 256>(sdata, KPROC, pidx, pval);
    sort_desc(pval, pidx, KPROC);           // jax top_k output order

    if (tid < KPROC) sexp[tid] = expf(pval[tid] - pval[0]);
    __syncthreads();
    if (tid == 0) {
        float s = 0.f;
        for (int j = 0; j < KPROC; ++j) s += sexp[j];
        sdenom = s;
    }
    __syncthreads();
    const float denom = sdenom;
    if (tid < KPROC) pval[tid] = __fdiv_rn(sexp[tid], denom);
    __syncthreads();

    float acc = 0.f;
    #pragma unroll 16
    for (int j = 0; j < KPROC; ++j)
        acc = fmaf(pval[j], PV[(size_t)pidx[j] * DPV + tid], acc);
    g_aggT[(size_t)tid * TOK + t] = acc;    // transposed (k-major for gemm3)
}

// ---------------------------------------------------------------------------
// Stage 3 (R11 version): top-256 of 2048 + combine in ascending-index slot
// order, cols (2tid, 2tid+1) via FFMA2. toff selects token range.
// ---------------------------------------------------------------------------
__global__ __launch_bounds__(256) void k_stage3(const float* __restrict__ OP,
                                                float* __restrict__ out,
                                                int toff) {
    __shared__ float sdata[NOUT];
    __shared__ int   sidx[KOUT];
    __shared__ float sval[KOUT];
    const int t   = toff + blockIdx.x;
    const int tid = threadIdx.x;
    {
        const float4* row = (const float4*)(g_acts3 + (size_t)t * NOUT);
        ((float4*)sdata)[tid]       = row[tid];
        ((float4*)sdata)[tid + 256] = row[tid + 256];
    }
    __syncthreads();
    topk_fast<NOUT / 256>(sdata, KOUT, sidx, sval);

    unsigned long long A = 0ull;            // cols (2tid, 2tid+1)
    #pragma unroll 16
    for (int j = 0; j < KOUT; ++j) {        // ascending-index slot order
        const unsigned long long v = dup2(sval[j]);
        const float* p = OP + (size_t)sidx[j] * DMODEL;
        unsigned long long pw = *(const unsigned long long*)(p + 2 * tid);
        ffma2(A, v, pw);
    }
    float2 o = unpack2(A);
    *(float2*)(out + (size_t)t * DMODEL + 2 * tid) = o;
}

// persistent stream/events (host-side objects only; created once)
static cudaStream_t g_s2 = nullptr;
static cudaEvent_t  g_evFork = nullptr, g_evJoin = nullptr;

extern "C" void kernel_launch(void* const* d_in, const int* in_sizes, int n_in,
                              void* d_out, int out_size) {
    const float* x   = (const float*)d_in[0];  // [2,1024,512]
    const float* ip  = (const float*)d_in[1];  // [2048,512]
    const float* piw = (const float*)d_in[2];  // [1024,2048]
    const float* pv  = (const float*)d_in[3];  // [1024,256]
    const float* oiw = (const float*)d_in[4];  // [2048,256]
    const float* op  = (const float*)d_in[5];  // [2048,512]
    float* out = (float*)d_out;                // [2,1024,512]

    float* xT   = nullptr; cudaGetSymbolAddress((void**)&xT,   g_xT);
    float* ipT  = nullptr; cudaGetSymbolAddress((void**)&ipT,  g_ipT);
    float* oiwT = nullptr; cudaGetSymbolAddress((void**)&oiwT, g_oiwT);
    float* a1p  = nullptr; cudaGetSymbolAddress((void**)&a1p,  g_acts1);
    float* aggT = nullptr; cudaGetSymbolAddress((void**)&aggT, g_aggT);
    float* a3p  = nullptr; cudaGetSymbolAddress((void**)&a3p,  g_acts3);

    const int GEMM_SMEM = 3 * 2 * 32 * 128 * 4;   // 96 KB
    static bool init_done = false;
    if (!init_done) {
        cudaFuncSetAttribute(k_gemm<DMODEL>,
            cudaFuncAttributeMaxDynamicSharedMemorySize, GEMM_SMEM);
        cudaFuncSetAttribute(k_gemm<DPV>,
            cudaFuncAttributeMaxDynamicSharedMemorySize, GEMM_SMEM);
        cudaStreamCreateWithFlags(&g_s2, cudaStreamNonBlocking);
        cudaEventCreateWithFlags(&g_evFork, cudaEventDisableTiming);
        cudaEventCreateWithFlags(&g_evJoin, cudaEventDisableTiming);
        init_done = true;
    }

    const int HTOK = TOK / 2;   // 1024

    // ---- serial trunk (identical to R11) --------------------------------
    k_transp_all<<<4608, dim3(32, 8)>>>(x, ip, oiw, piw);
    k_gemm<DMODEL><<<dim3(NIN / 128, TOK / 128), 256, GEMM_SMEM>>>(
        xT, ipT, a1p, TOK, NIN, 0);
    k_stage2<<<TOK, 256>>>(pv);

    // gemm3 on token half A
    k_gemm<DPV><<<dim3(NOUT / 128, HTOK / 128), 256, GEMM_SMEM>>>(
        aggT, oiwT, a3p, TOK, NOUT, 0);

    // fork: gemm3(B) [FMA-bound] overlaps stage3(A) [L2-bound]
    cudaEventRecord(g_evFork, 0);
    cudaStreamWaitEvent(g_s2, g_evFork, 0);
    k_gemm<DPV><<<dim3(NOUT / 128, HTOK / 128), 256, GEMM_SMEM, g_s2>>>(
        aggT, oiwT, a3p, TOK, NOUT, HTOK);

    k_stage3<<<HTOK, 256>>>(op, out, 0);        // half A on stream 0

    // join: stage3(B) needs gemm3(B)
    cudaEventRecord(g_evJoin, g_s2);
    cudaStreamWaitEvent(0, g_evJoin, 0);
    k_stage3<<<HTOK, 256>>>(op, out, HTOK);     // half B on stream 0
}

// round 15
// speedup vs baseline: 1.5443x; 1.0775x over previous
#include <cuda_runtime.h>
#include <cstdint>

// Problem dims (fixed by the dataset)
#define TOK    2048   // B*S
#define DMODEL 512
#define NIN    2048
#define NPROC  1024
#define DPV    256
#define NOUT   2048
#define KIN    256
#define KPROC  128
#define KOUT   256

// Scratch (device globals — no dynamic allocation allowed)
__device__ float g_acts1[TOK * NIN];      // gelu(x @ IP^T)       16 MB
__device__ float g_Wt[NIN * NPROC];       // PIW^T                 8 MB
__device__ float g_xT[DMODEL * TOK];      // x^T   (k-major A)     4 MB
__device__ float g_ipT[DMODEL * NIN];     // IP^T  (k-major B)     4 MB
__device__ float g_oiwT[DPV * NOUT];      // OIW^T (k-major B)     2 MB
__device__ float g_aggT[DPV * TOK];       // agg^T (k-major A)     2 MB
__device__ float g_acts3[TOK * NOUT];     // gelu(agg @ OIW^T)    16 MB

// ---------------------------------------------------------------------------
// XLA's f32 erf (what jax.lax.erf runs): clamp to [-4,4], x*P(x^2)/Q(x^2).
// ---------------------------------------------------------------------------
__device__ __forceinline__ float erf_xla(float x) {
    x = fminf(fmaxf(x, -4.0f), 4.0f);
    float x2 = x * x;
    float p = fmaf(x2, 0.00022905065861350646f, 0.0034082910107109506f);
    p = fmaf(x2, p, 0.050955695062380861f);
    p = fmaf(x2, p, 0.18520832239976145f);
    p = fmaf(x2, p, 1.128379143519084f);
    p = x * p;
    float q = fmaf(x2, -1.1791602954361697e-7f, 2.3547966471313185e-05f);
    q = fmaf(x2, q, 0.0010179625278914885f);
    q = fmaf(x2, q, 0.014070470171167667f);
    q = fmaf(x2, q, 0.11098505178285362f);
    q = fmaf(x2, q, 0.49746925110067538f);
    q = fmaf(x2, q, 1.0f);
    return __fdiv_rn(p, q);
}

// jax.nn.gelu(approximate=False): (x * (erf(x / sqrt2) + 1)) / 2
__device__ __forceinline__ float gelu_f(float x) {
    float t = __fdiv_rn(x, 1.41421356237309504880f);
    float e = erf_xla(t);
    return x * (e + 1.0f) * 0.5f;
}

// order-preserving float -> uint key (larger float => larger key)
__device__ __forceinline__ unsigned fkey(float f) {
    unsigned b = __float_as_uint(f);
    return b ^ ((b & 0x80000000u) ? 0xFFFFFFFFu : 0x80000000u);
}

// ---------------------------------------------------------------------------
// Packed f32x2 helpers. Each half = independent IEEE rn FMA, bitwise
// identical to scalar fmaf on that half.
// ---------------------------------------------------------------------------
__device__ __forceinline__ void ffma2(unsigned long long& d,
                                      unsigned long long a,
                                      unsigned long long b) {
    asm("fma.rn.f32x2 %0, %1, %2, %0;" : "+l"(d) : "l"(a), "l"(b));
}
__device__ __forceinline__ unsigned long long dup2(float x) {
    unsigned long long r;
    asm("mov.b64 %0, {%1, %1};" : "=l"(r) : "f"(x));
    return r;
}
__device__ __forceinline__ float2 unpack2(unsigned long long v) {
    float2 f;
    asm("mov.b64 {%0, %1}, %2;" : "=f"(f.x), "=f"(f.y) : "l"(v));
    return f;
}

// cp.async helpers
__device__ __forceinline__ void cp16(uint32_t smem, const void* g) {
    asm volatile("cp.async.ca.shared.global [%0], [%1], 16;"
                 :: "r"(smem), "l"(g));
}
__device__ __forceinline__ void cp_commit() {
    asm volatile("cp.async.commit_group;");
}
__device__ __forceinline__ void cp_wait1() {
    asm volatile("cp.async.wait_group 1;");
}

// ---------------------------------------------------------------------------
// Warp-shuffle scan primitives
// ---------------------------------------------------------------------------
__device__ __forceinline__ unsigned warp_suffix_incl(unsigned v, int lane) {
    #pragma unroll
    for (int off = 1; off < 32; off <<= 1) {
        unsigned o = __shfl_down_sync(0xffffffffu, v, off);
        if (lane + off < 32) v += o;
    }
    return v;
}
__device__ __forceinline__ unsigned warp_prefix_incl(unsigned v, int lane) {
    #pragma unroll
    for (int off = 1; off < 32; off <<= 1) {
        unsigned o = __shfl_up_sync(0xffffffffu, v, off);
        if (lane >= off) v += o;
    }
    return v;
}

// block-wide (256 thr) exclusive prefix sum; s_wsum is 8-entry scratch
__device__ __forceinline__ unsigned block_prefix_excl(unsigned x, unsigned* s_wsum) {
    const int tid = threadIdx.x, lane = tid & 31, wid = tid >> 5;
    unsigned v = warp_prefix_incl(x, lane);
    __syncthreads();
    if (lane == 31) s_wsum[wid] = v;
    __syncthreads();
    unsigned add = 0;
    #pragma unroll
    for (int w = 0; w < 8; ++w) if (w < wid) add += s_wsum[w];
    return v + add - x;
}

// ---------------------------------------------------------------------------
// Exact top-k for one row in shared memory. Block = 256 threads.
// jax.lax.top_k set semantics (lowest index wins ties); slots in
// ascending-index order. n = EPB*256.
// ---------------------------------------------------------------------------
template <int EPB>
__device__ void topk_fast(const float* sdata, int k, int* out_idx, float* out_val)
{
    __shared__ unsigned s_cnt[256];
    __shared__ unsigned s_wsum[8];
    __shared__ unsigned s_bin;
    __shared__ unsigned s_kneed;
    const int tid  = threadIdx.x, lane = tid & 31, wid = tid >> 5;
    const int base = tid * EPB;

    unsigned key[EPB];
    #pragma unroll
    for (int e = 0; e < EPB; ++e) key[e] = fkey(sdata[base + e]);

    if (tid == 0) s_kneed = (unsigned)k;
    unsigned prefix = 0;

    #pragma unroll
    for (int pass = 0; pass < 4; ++pass) {
        const int shift = 24 - 8 * pass;
        s_cnt[tid] = 0;
        __syncthreads();
        #pragma unroll
        for (int e = 0; e < EPB; ++e) {
            bool m;
            if (pass == 0) m = true;
            else           m = ((key[e] >> (shift + 8)) == prefix);
            if (m) atomicAdd(&s_cnt[(key[e] >> shift) & 255u], 1u);
        }
        __syncthreads();
        unsigned own = s_cnt[tid];
        unsigned v   = warp_suffix_incl(own, lane);   // lane0 = warp total
        if (lane == 0) s_wsum[wid] = v;
        __syncthreads();
        unsigned add = 0;
        #pragma unroll
        for (int w = 0; w < 8; ++w) if (w > wid) add += s_wsum[w];
        v += add;                                     // inclusive suffix over 256 bins
        unsigned kneed = s_kneed;
        __syncthreads();
        if (v >= kneed && (v - own) < kneed) {
            s_bin   = (unsigned)tid;
            s_kneed = kneed - (v - own);
        }
        __syncthreads();
        prefix = (prefix << 8) | s_bin;
    }
    const unsigned thr = prefix;
    const unsigned r   = s_kneed;

    unsigned ceq = 0, cgt = 0;
    #pragma unroll
    for (int e = 0; e < EPB; ++e) {
        if (key[e] > thr) cgt++;
        else if (key[e] == thr) ceq++;
    }
    unsigned eq_base = block_prefix_excl(ceq, s_wsum);
    unsigned eq_keep = (eq_base < r) ? min(r - eq_base, ceq) : 0u;
    unsigned slot    = block_prefix_excl(cgt + eq_keep, s_wsum);

    unsigned eqo = eq_base;
    #pragma unroll
    for (int e = 0; e < EPB; ++e) {
        bool keep = false;
        if (key[e] > thr) keep = true;
        else if (key[e] == thr) { keep = (eqo < r); eqo++; }
        if (keep) { out_idx[slot] = base + e; out_val[slot] = sdata[base + e]; slot++; }
    }
    __syncthreads();
}

// ---------------------------------------------------------------------------
// Bitonic sort of (val,idx) pairs, length L (power of 2 <= 256), 256 threads.
// Final order: descending value; ties -> ascending index (jax top_k order).
// ---------------------------------------------------------------------------
__device__ void sort_desc(float* v, int* idx, int L) {
    const int tid = threadIdx.x;
    for (int size = 2; size <= L; size <<= 1) {
        for (int stride = size >> 1; stride > 0; stride >>= 1) {
            __syncthreads();
            for (int i = tid; i < (L >> 1); i += 256) {
                int lo = 2 * i - (i & (stride - 1));
                int hi = lo + stride;
                float va = v[lo], vb = v[hi];
                int   ia = idx[lo], ib = idx[hi];
                bool aBeforeB = (va > vb) || (va == vb && ia < ib);
                bool dirDesc  = ((lo & size) == 0);
                if (dirDesc ? !aBeforeB : aBeforeB) {
                    v[lo] = vb; v[hi] = va;
                    idx[lo] = ib; idx[hi] = ia;
                }
            }
        }
    }
    __syncthreads();
}

// ---------------------------------------------------------------------------
// All four input transposes fused in one launch.
// ---------------------------------------------------------------------------
__global__ void k_transp_all(const float* __restrict__ x,
                             const float* __restrict__ ip,
                             const float* __restrict__ oiw,
                             const float* __restrict__ piw) {
    __shared__ float tile[32][33];
    int b = blockIdx.x;
    const float* src; float* dst; int R, C, bx, by;
    if (b < 1024)      { src = x;   dst = g_xT;   R = TOK;   C = DMODEL; bx = b & 15;  by = b >> 4; }
    else if (b < 2048) { b -= 1024; src = ip;  dst = g_ipT;  R = NIN;   C = DMODEL; bx = b & 15;  by = b >> 4; }
    else if (b < 2560) { b -= 2048; src = oiw; dst = g_oiwT; R = NOUT;  C = DPV;    bx = b & 7;   by = b >> 3; }
    else               { b -= 2560; src = piw; dst = g_Wt;   R = NPROC; C = NIN;    bx = b & 63;  by = b >> 6; }
    int c0 = bx * 32, r0 = by * 32;
    int tx = threadIdx.x, ty = threadIdx.y;
    #pragma unroll
    for (int j = 0; j < 32; j += 8)
        tile[ty + j][tx] = src[(size_t)(r0 + ty + j) * C + c0 + tx];
    __syncthreads();
    #pragma unroll
    for (int j = 0; j < 32; j += 8)
        dst[(size_t)(c0 + ty + j) * R + r0 + tx] = tile[tx][ty + j];
}

// ---------------------------------------------------------------------------
// GEMM with k-major operands (at fp32 MAC roofline — unchanged from R9/R11).
// ---------------------------------------------------------------------------
template <int K>
__global__ __launch_bounds__(256, 2) void k_gemm(
    const float* __restrict__ At,   // [K][Mtot]
    const float* __restrict__ Bt,   // [K][Ntot]
    float* __restrict__ C,          // [Mtot][Ntot]
    int Mtot, int Ntot)
{
    constexpr int BK = 32, STAGES = 3, NT = K / BK;
    constexpr int TILE_FLOATS = BK * 128;
    extern __shared__ __align__(16) float smem_dyn[];
    float* sAq = smem_dyn;
    float* sBq = smem_dyn + STAGES * TILE_FLOATS;
    const int tid = threadIdx.x;
    const int tx  = tid & 15, ty = tid >> 4;
    const int m0  = blockIdx.y * 128;
    const int n0  = blockIdx.x * 128;

    const int cr = tid >> 5;
    const int cc = (tid & 31) << 2;
    const uint32_t sA0 = (uint32_t)__cvta_generic_to_shared(sAq);
    const uint32_t sB0 = (uint32_t)__cvta_generic_to_shared(sBq);
    uint32_t so[4];
    #pragma unroll
    for (int i = 0; i < 4; ++i) so[i] = (uint32_t)(((cr + 8 * i) * 128 + cc) * 4);

    unsigned long long acc2[8][4];
    #pragma unroll
    for (int i = 0; i < 8; ++i)
        #pragma unroll
        for (int j = 0; j < 4; ++j) acc2[i][j] = 0ull;

    #pragma unroll
    for (int s = 0; s < STAGES - 1; ++s) {
        const size_t gk = (size_t)s * BK;
        #pragma unroll
        for (int i = 0; i < 4; ++i) {
            cp16(sA0 + s * (TILE_FLOATS * 4) + so[i],
                 At + (gk + cr + 8 * i) * (size_t)Mtot + m0 + cc);
            cp16(sB0 + s * (TILE_FLOATS * 4) + so[i],
                 Bt + (gk + cr + 8 * i) * (size_t)Ntot + n0 + cc);
        }
        cp_commit();
    }

    int stage = 0;
    for (int kt = 0; kt < NT; ++kt) {
        cp_wait1();
        __syncthreads();

        if (kt + STAGES - 1 < NT) {
            int ps = (stage + STAGES - 1) % STAGES;
            const size_t gk = (size_t)(kt + STAGES - 1) * BK;
            #pragma unroll
            for (int i = 0; i < 4; ++i) {
                cp16(sA0 + ps * (TILE_FLOATS * 4) + so[i],
                     At + (gk + cr + 8 * i) * (size_t)Mtot + m0 + cc);
                cp16(sB0 + ps * (TILE_FLOATS * 4) + so[i],
                     Bt + (gk + cr + 8 * i) * (size_t)Ntot + n0 + cc);
            }
        }
        cp_commit();

        const float* a_s = sAq + stage * TILE_FLOATS;
        const float* b_s = sBq + stage * TILE_FLOATS;
        #pragma unroll
        for (int kk = 0; kk < BK; ++kk) {
            float4 a0 = *(const float4*)&a_s[kk * 128 + ty * 8];
            float4 a1 = *(const float4*)&a_s[kk * 128 + ty * 8 + 4];
            ulonglong2 b01 = *(const ulonglong2*)&b_s[kk * 128 + tx * 8];
            ulonglong2 b23 = *(const ulonglong2*)&b_s[kk * 128 + tx * 8 + 4];
            unsigned long long bb[4] = {b01.x, b01.y, b23.x, b23.y};
            float ar[8] = {a0.x, a0.y, a0.z, a0.w, a1.x, a1.y, a1.z, a1.w};
            #pragma unroll
            for (int i = 0; i < 8; ++i) {
                unsigned long long ad = dup2(ar[i]);
                #pragma unroll
                for (int j = 0; j < 4; ++j)
                    ffma2(acc2[i][j], ad, bb[j]);
            }
        }
        stage = (stage + 1) % STAGES;
    }

    #pragma unroll
    for (int i = 0; i < 8; ++i) {
        float* Cr = C + (size_t)(m0 + ty * 8 + i) * Ntot + n0 + tx * 8;
        float2 p0 = unpack2(acc2[i][0]);
        float2 p1 = unpack2(acc2[i][1]);
        float2 p2 = unpack2(acc2[i][2]);
        float2 p3 = unpack2(acc2[i][3]);
        float4 o0, o1;
        o0.x = gelu_f(p0.x); o0.y = gelu_f(p0.y);
        o0.z = gelu_f(p1.x); o0.w = gelu_f(p1.y);
        o1.x = gelu_f(p2.x); o1.y = gelu_f(p2.y);
        o1.z = gelu_f(p3.x); o1.w = gelu_f(p3.y);
        *(float4*)Cr       = o0;
        *(float4*)(Cr + 4) = o1;
    }
}

// ---------------------------------------------------------------------------
// Stage 1+2 fused (R11 numerics, launch_bounds(256,8) -> regs<=32 for 8
// CTAs/SM): acts1 row -> top-256 -> L2 gather-matmul (FFMA2 col pairs
// {2t,2t+1},{2t+512,2t+513}, ascending-n chains) -> gelu -> top-128 ->
// sort desc -> softmax (sequential, jax order) -> PV gather -> g_aggT.
// ---------------------------------------------------------------------------
__global__ __launch_bounds__(256, 8) void k_stage2(const float* __restrict__ PV) {
    __shared__ float sdata[NIN];
    __shared__ int   sIdx[KIN];
    __shared__ float sVal[KIN];
    __shared__ int   pidx[KPROC];
    __shared__ float pval[KPROC];
    __shared__ float sexp[KPROC];
    __shared__ float sdenom;
    const int t   = blockIdx.x;
    const int tid = threadIdx.x;

    {
        const float4* row = (const float4*)(g_acts1 + (size_t)t * NIN);
        float4 r0 = row[tid];
        float4 r1 = row[tid + 256];
        ((float4*)sdata)[tid]       = r0;
        ((float4*)sdata)[tid + 256] = r1;
    }
    __syncthreads();

    topk_fast<NIN / 256>(sdata, KIN, sIdx, sVal);

    unsigned long long A0 = 0ull, A1 = 0ull;   // col pairs (2tid,2tid+1), (+512)
    #pragma unroll 16
    for (int j = 0; j < KIN; ++j) {            // ascending n (reference order)
        const unsigned long long v = dup2(sVal[j]);
        const float* w = g_Wt + (size_t)sIdx[j] * NPROC;
        unsigned long long w0 = *(const unsigned long long*)(w + 2 * tid);
        unsigned long long w1 = *(const unsigned long long*)(w + 2 * tid + 512);
        ffma2(A0, v, w0);
        ffma2(A1, v, w1);
    }
    __syncthreads();
    {
        float2 p0 = unpack2(A0);
        float2 p1 = unpack2(A1);
        sdata[2 * tid]           = gelu_f(p0.x);
        sdata[2 * tid + 1]       = gelu_f(p0.y);
        sdata[2 * tid + 512]     = gelu_f(p1.x);
        sdata[2 * tid + 513]     = gelu_f(p1.y);
    }
    __syncthreads();

    topk_fast<NPROC / 256>(sdata, KPROC, pidx, pval);
    sort_desc(pval, pidx, KPROC);           // jax top_k output order

    if (tid < KPROC) sexp[tid] = expf(pval[tid] - pval[0]);
    __syncthreads();
    if (tid == 0) {
        float s = 0.f;
        for (int j = 0; j < KPROC; ++j) s += sexp[j];
        sdenom = s;
    }
    __syncthreads();
    const float denom = sdenom;
    if (tid < KPROC) pval[tid] = __fdiv_rn(sexp[tid], denom);
    __syncthreads();

    float acc = 0.f;
    #pragma unroll 16
    for (int j = 0; j < KPROC; ++j)
        acc = fmaf(pval[j], PV[(size_t)pidx[j] * DPV + tid], acc);
    g_aggT[(size_t)tid * TOK + t] = acc;    // transposed (k-major for gemm3)
}

// ---------------------------------------------------------------------------
// Stage 3 (R11 numerics, launch_bounds(256,8)): top-256 of 2048 + combine
// in ascending-index slot order, cols (2tid, 2tid+1) via FFMA2.
// ---------------------------------------------------------------------------
__global__ __launch_bounds__(256, 8) void k_stage3(const float* __restrict__ OP,
                                                   float* __restrict__ out) {
    __shared__ float sdata[NOUT];
    __shared__ int   sidx[KOUT];
    __shared__ float sval[KOUT];
    const int t   = blockIdx.x;
    const int tid = threadIdx.x;
    {
        const float4* row = (const float4*)(g_acts3 + (size_t)t * NOUT);
        ((float4*)sdata)[tid]       = row[tid];
        ((float4*)sdata)[tid + 256] = row[tid + 256];
    }
    __syncthreads();
    topk_fast<NOUT / 256>(sdata, KOUT, sidx, sval);

    unsigned long long A = 0ull;            // cols (2tid, 2tid+1)
    #pragma unroll 16
    for (int j = 0; j < KOUT; ++j) {        // ascending-index slot order
        const unsigned long long v = dup2(sval[j]);
        const float* p = OP + (size_t)sidx[j] * DMODEL;
        unsigned long long pw = *(const unsigned long long*)(p + 2 * tid);
        ffma2(A, v, pw);
    }
    float2 o = unpack2(A);
    *(float2*)(out + (size_t)t * DMODEL + 2 * tid) = o;
}

extern "C" void kernel_launch(void* const* d_in, const int* in_sizes, int n_in,
                              void* d_out, int out_size) {
    const float* x   = (const float*)d_in[0];  // [2,1024,512]
    const float* ip  = (const float*)d_in[1];  // [2048,512]
    const float* piw = (const float*)d_in[2];  // [1024,2048]
    const float* pv  = (const float*)d_in[3];  // [1024,256]
    const float* oiw = (const float*)d_in[4];  // [2048,256]
    const float* op  = (const float*)d_in[5];  // [2048,512]
    float* out = (float*)d_out;                // [2,1024,512]

    float* xT   = nullptr; cudaGetSymbolAddress((void**)&xT,   g_xT);
    float* ipT  = nullptr; cudaGetSymbolAddress((void**)&ipT,  g_ipT);
    float* oiwT = nullptr; cudaGetSymbolAddress((void**)&oiwT, g_oiwT);
    float* a1p  = nullptr; cudaGetSymbolAddress((void**)&a1p,  g_acts1);
    float* aggT = nullptr; cudaGetSymbolAddress((void**)&aggT, g_aggT);
    float* a3p  = nullptr; cudaGetSymbolAddress((void**)&a3p,  g_acts3);

    const int GEMM_SMEM = 3 * 2 * 32 * 128 * 4;   // 96 KB
    static bool attr_set = false;
    if (!attr_set) {
        cudaFuncSetAttribute(k_gemm<DMODEL>,
            cudaFuncAttributeMaxDynamicSharedMemorySize, GEMM_SMEM);
        cudaFuncSetAttribute(k_gemm<DPV>,
            cudaFuncAttributeMaxDynamicSharedMemorySize, GEMM_SMEM);
        attr_set = true;
    }

    k_transp_all<<<4608, dim3(32, 8)>>>(x, ip, oiw, piw);
    k_gemm<DMODEL><<<dim3(NIN / 128, TOK / 128), 256, GEMM_SMEM>>>(xT, ipT, a1p, TOK, NIN);
    k_stage2<<<TOK, 256>>>(pv);
    k_gemm<DPV><<<dim3(NOUT / 128, TOK / 128), 256, GEMM_SMEM>>>(aggT, oiwT, a3p, TOK, NOUT);
    k_stage3<<<TOK, 256>>>(op, out);
}